// round 15
// baseline (speedup 1.0000x reference)
#include <cuda_runtime.h>
#include <cuda_fp16.h>
#include <cstdint>

#define ATT_SCALE 0.08838834764831845f            // 128^-0.5
#define QSCALE (0.08838834764831845f * 1.4426950408889634f)   // fold log2(e): exp -> exp2

// Scratch (allocation-free rule: __device__ globals)
__device__ __half g_qh [16777216];   // [64][2048][128] fp16 (pre-scaled by QSCALE)
__device__ __half g_kh [16777216];   // [64][2048][128] fp16, chunk-swizzled rows
__device__ __half g_vh [16777216];   // [64][2048][128] fp16, chunk-swizzled rows

// ===========================================================================
// helpers
// ===========================================================================
__device__ __forceinline__ uint32_t smem_u32(const void* p) {
    uint32_t a;
    asm("{ .reg .u64 t; cvta.to.shared.u64 t, %1; cvt.u32.u64 %0, t; }"
        : "=r"(a) : "l"(p));
    return a;
}
__device__ __forceinline__ void mma16h(float* d, const uint32_t* a,
                                       uint32_t b0, uint32_t b1) {
    asm volatile(
        "mma.sync.aligned.m16n8k16.row.col.f32.f16.f16.f32 "
        "{%0,%1,%2,%3}, {%4,%5,%6,%7}, {%8,%9}, {%0,%1,%2,%3};"
        : "+f"(d[0]), "+f"(d[1]), "+f"(d[2]), "+f"(d[3])
        : "r"(a[0]), "r"(a[1]), "r"(a[2]), "r"(a[3]), "r"(b0), "r"(b1));
}
__device__ __forceinline__ void ldmx4(uint32_t* r, uint32_t addr) {
    asm volatile("ldmatrix.sync.aligned.m8n8.x4.shared.b16 {%0,%1,%2,%3}, [%4];"
                 : "=r"(r[0]), "=r"(r[1]), "=r"(r[2]), "=r"(r[3]) : "r"(addr));
}
__device__ __forceinline__ void ldmx4t(uint32_t* r, uint32_t addr) {
    asm volatile("ldmatrix.sync.aligned.m8n8.x4.trans.shared.b16 {%0,%1,%2,%3}, [%4];"
                 : "=r"(r[0]), "=r"(r[1]), "=r"(r[2]), "=r"(r[3]) : "r"(addr));
}
__device__ __forceinline__ uint32_t f2h2(float hi, float lo) {   // pack: lo in low half
    uint32_t r;
    asm("cvt.rn.f16x2.f32 %0, %1, %2;" : "=r"(r) : "f"(hi), "f"(lo));
    return r;
}
__device__ __forceinline__ uint32_t ex2h2(uint32_t x) {          // 2^x per half
    uint32_t r;
    asm("ex2.approx.f16x2 %0, %1;" : "=r"(r) : "r"(x));
    return r;
}
__device__ __forceinline__ void bulk_g2s(uint32_t dst, const void* src,
                                         uint32_t bytes, uint32_t mbar) {
    asm volatile(
        "cp.async.bulk.shared::cluster.global.mbarrier::complete_tx::bytes "
        "[%0], [%1], %2, [%3];"
        :: "r"(dst), "l"(src), "r"(bytes), "r"(mbar) : "memory");
}
#define MBARRIER_INIT(addr, cnt) \
    asm volatile("mbarrier.init.shared.b64 [%0], %1;" \
        :: "r"((uint32_t)(addr)), "r"((uint32_t)(cnt)) : "memory")
#define MBARRIER_EXPECT_TX(addr, tx) \
    asm volatile("mbarrier.arrive.expect_tx.shared.b64 _, [%0], %1;" \
        :: "r"((uint32_t)(addr)), "r"((uint32_t)(tx)) : "memory")
#define FENCE_PROXY_ASYNC() \
    asm volatile("fence.proxy.async.shared::cta;" ::: "memory")
#define MBARRIER_WAIT_PARITY(mbar_smem_addr, phase_parity) do { \
    uint32_t _mbar = (uint32_t)(mbar_smem_addr); \
    uint32_t _parity = (uint32_t)(phase_parity); \
    uint32_t _done; \
    asm volatile( \
        "{\n\t.reg .pred p;\n\t" \
        "mbarrier.try_wait.parity.shared.b64 p, [%1], %2;\n\t" \
        "selp.b32 %0, 1, 0, p;\n\t}" \
        : "=r"(_done) : "r"(_mbar), "r"(_parity) : "memory"); \
    if (!_done) { \
        asm volatile( \
            "{\n\t.reg .pred P1;\n\t" \
            "WAIT_LOOP_%=:\n\t" \
            "mbarrier.try_wait.parity.shared.b64 P1, [%0], %1, 0x989680;\n\t" \
            "@P1 bra.uni WAIT_DONE_%=;\n\t" \
            "bra.uni WAIT_LOOP_%=;\n\t" \
            "WAIT_DONE_%=:\n\t}" \
            :: "r"(_mbar), "r"(_parity) : "memory"); \
    } \
} while(0)

// chunk swizzle: 16B chunk c of row r -> (c&8) | ((c ^ (r&7)) & 7)
__device__ __forceinline__ int swz(int c, int r) {
    return (c & 8) | ((c ^ (r & 7)) & 7);
}

static constexpr int PL = 34816;   // smem plane: [128][136] halves

// ===========================================================================
// q projection: plain fp16 1-mma, fp16 out (unswizzled), *QSCALE
//   B-frags via ldmx4 (nt pairs).
// ===========================================================================
__global__ void __launch_bounds__(256, 2)
proj_q_kernel(const float* __restrict__ A,
              const float* __restrict__ W,
              __half* __restrict__ Ch, float oscale)
{
    extern __shared__ __align__(16) char smc[];
    const uint32_t sb = smem_u32(smc);

    const int tid  = threadIdx.x;
    const int w    = tid >> 5;
    const int lane = tid & 31;
    const int g    = lane >> 2;
    const int tg   = lane & 3;
    const int m0   = blockIdx.y << 7;

#pragma unroll
    for (int it = 0; it < 16; it++) {
        int idx = tid + (it << 8);
        int r = idx >> 5, c = idx & 31;
        float4 va = *(const float4*)&A[(size_t)(m0 + r) * 128 + (c << 2)];
        __half2 a01 = __floats2half2_rn(va.x, va.y);
        __half2 a23 = __floats2half2_rn(va.z, va.w);
        *(uint2*)(smc + r * 272 + (c << 3)) =
            make_uint2(*(uint32_t*)&a01, *(uint32_t*)&a23);
        float4 vw = *(const float4*)&W[(size_t)r * 128 + (c << 2)];
        __half2 w01 = __floats2half2_rn(vw.x, vw.y);
        __half2 w23 = __floats2half2_rn(vw.z, vw.w);
        *(uint2*)(smc + PL + r * 272 + (c << 3)) =
            make_uint2(*(uint32_t*)&w01, *(uint32_t*)&w23);
    }
    __syncthreads();

    float o[16][4];
#pragma unroll
    for (int nt = 0; nt < 16; nt++)
#pragma unroll
        for (int c = 0; c < 4; c++) o[nt][c] = 0.f;

    const uint32_t abase = sb + ((w << 4) + (lane & 15)) * 272
                         + ((lane >> 4) << 4);
    const uint32_t bbase4 = sb + PL
        + (((lane >> 4) << 3) + (lane & 7)) * 272 + (((lane >> 3) & 1) << 4);

#pragma unroll
    for (int kt = 0; kt < 8; kt++) {
        uint32_t ah[4];
        ldmx4(ah, abase + (kt << 5));
#pragma unroll
        for (int ntp = 0; ntp < 8; ntp++) {
            uint32_t b[4];
            ldmx4(b, bbase4 + ntp * 4352 + (kt << 5));
            mma16h(o[2 * ntp],     ah, b[0], b[1]);
            mma16h(o[2 * ntp + 1], ah, b[2], b[3]);
        }
    }

    const int r0 = m0 + (w << 4) + g;
#pragma unroll
    for (int nt = 0; nt < 16; nt++) {
        const int col = (nt << 3) + (tg << 1);
        *(__half2*)&Ch[(size_t)r0 * 128 + col] =
            __floats2half2_rn(o[nt][0] * oscale, o[nt][1] * oscale);
        *(__half2*)&Ch[(size_t)(r0 + 8) * 128 + col] =
            __floats2half2_rn(o[nt][2] * oscale, o[nt][3] * oscale);
    }
}

// ===========================================================================
// merged k+v projection: stage kv A-tile ONCE (hi/lo), two W passes.
//   B-frags via ldmx4 (nt pairs).
// ===========================================================================
__global__ void __launch_bounds__(256, 2)
proj_kv_kernel(const float* __restrict__ A,
               const float* __restrict__ Wkv,
               __half* __restrict__ kh, __half* __restrict__ vh)
{
    extern __shared__ __align__(16) char smc[];
    const uint32_t sb = smem_u32(smc);
    // planes: A_hi @ 0, A_lo @ PL, W @ 2*PL

    const int tid  = threadIdx.x;
    const int w    = tid >> 5;
    const int lane = tid & 31;
    const int g    = lane >> 2;
    const int tg   = lane & 3;
    const int m0   = blockIdx.y << 7;

#pragma unroll
    for (int it = 0; it < 16; it++) {
        int idx = tid + (it << 8);
        int r = idx >> 5, c = idx & 31;
        float4 va = *(const float4*)&A[(size_t)(m0 + r) * 128 + (c << 2)];
        __half2 a01 = __floats2half2_rn(va.x, va.y);
        __half2 a23 = __floats2half2_rn(va.z, va.w);
        *(uint2*)(smc + r * 272 + (c << 3)) =
            make_uint2(*(uint32_t*)&a01, *(uint32_t*)&a23);
        __half2 l01 = __floats2half2_rn(va.x - __low2float(a01),
                                        va.y - __high2float(a01));
        __half2 l23 = __floats2half2_rn(va.z - __low2float(a23),
                                        va.w - __high2float(a23));
        *(uint2*)(smc + PL + r * 272 + (c << 3)) =
            make_uint2(*(uint32_t*)&l01, *(uint32_t*)&l23);
        float4 vw = *(const float4*)&Wkv[(size_t)r * 128 + (c << 2)];
        __half2 w01 = __floats2half2_rn(vw.x, vw.y);
        __half2 w23 = __floats2half2_rn(vw.z, vw.w);
        *(uint2*)(smc + 2 * PL + r * 272 + (c << 3)) =
            make_uint2(*(uint32_t*)&w01, *(uint32_t*)&w23);
    }
    __syncthreads();

    const uint32_t abase = sb + ((w << 4) + (lane & 15)) * 272
                         + ((lane >> 4) << 4);
    const uint32_t bbase4 = sb + 2 * PL
        + (((lane >> 4) << 3) + (lane & 7)) * 272 + (((lane >> 3) & 1) << 4);
    const int r0 = m0 + (w << 4) + g;

    // ---- pass 1: k' (1-mma) ----
    {
        float o[16][4];
#pragma unroll
        for (int nt = 0; nt < 16; nt++)
#pragma unroll
            for (int c = 0; c < 4; c++) o[nt][c] = 0.f;
#pragma unroll
        for (int kt = 0; kt < 8; kt++) {
            uint32_t ah[4];
            ldmx4(ah, abase + (kt << 5));
#pragma unroll
            for (int ntp = 0; ntp < 8; ntp++) {
                uint32_t b[4];
                ldmx4(b, bbase4 + ntp * 4352 + (kt << 5));
                mma16h(o[2 * ntp],     ah, b[0], b[1]);
                mma16h(o[2 * ntp + 1], ah, b[2], b[3]);
            }
        }
#pragma unroll
        for (int nt = 0; nt < 16; nt++) {
            const int col = (nt << 3) + (tg << 1);
            const int scol = (swz(col >> 3, r0) << 3) | (col & 7);
            *(__half2*)&kh[(size_t)r0 * 128 + scol] =
                __floats2half2_rn(o[nt][0], o[nt][1]);
            *(__half2*)&kh[(size_t)(r0 + 8) * 128 + scol] =
                __floats2half2_rn(o[nt][2], o[nt][3]);
        }
    }
    __syncthreads();

    // ---- restage W <- Wv ----
#pragma unroll
    for (int it = 0; it < 16; it++) {
        int idx = tid + (it << 8);
        int r = idx >> 5, c = idx & 31;
        float4 vw = *(const float4*)&Wkv[16384 + (size_t)r * 128 + (c << 2)];
        __half2 w01 = __floats2half2_rn(vw.x, vw.y);
        __half2 w23 = __floats2half2_rn(vw.z, vw.w);
        *(uint2*)(smc + 2 * PL + r * 272 + (c << 3)) =
            make_uint2(*(uint32_t*)&w01, *(uint32_t*)&w23);
    }
    __syncthreads();

    // ---- pass 2: v' (2-mma split) ----
    {
        float o[16][4];
#pragma unroll
        for (int nt = 0; nt < 16; nt++)
#pragma unroll
            for (int c = 0; c < 4; c++) o[nt][c] = 0.f;
#pragma unroll
        for (int kt = 0; kt < 8; kt++) {
            uint32_t ah[4], al[4];
            ldmx4(ah, abase + (kt << 5));
            ldmx4(al, abase + PL + (kt << 5));
#pragma unroll
            for (int ntp = 0; ntp < 8; ntp++) {
                uint32_t b[4];
                ldmx4(b, bbase4 + ntp * 4352 + (kt << 5));
                mma16h(o[2 * ntp],     ah, b[0], b[1]);
                mma16h(o[2 * ntp],     al, b[0], b[1]);
                mma16h(o[2 * ntp + 1], ah, b[2], b[3]);
                mma16h(o[2 * ntp + 1], al, b[2], b[3]);
            }
        }
#pragma unroll
        for (int nt = 0; nt < 16; nt++) {
            const int col = (nt << 3) + (tg << 1);
            const int scol = (swz(col >> 3, r0) << 3) | (col & 7);
            *(__half2*)&vh[(size_t)r0 * 128 + scol] =
                __floats2half2_rn(o[nt][0], o[nt][1]);
            *(__half2*)&vh[(size_t)(r0 + 8) * 128 + scol] =
                __floats2half2_rn(o[nt][2], o[nt][3]);
        }
    }
}

// ===========================================================================
// flash attention + fused out-projection. 3-deep K/V bulk pipeline
// (2 tiles of copy slack), per-tile syncthreads release (proven structure).
// ===========================================================================
static constexpr int KB_  = 0;        // K bufs: 3 x 16384 (Q stage + Wout overlay)
static constexpr int VB_  = 49152;    // V bufs: 3 x 16384
static constexpr int MB_  = 98304;    // 3 mbarriers
static constexpr int ATT_BYTES = 98336;

__global__ void __launch_bounds__(128, 2)
attn_mma_kernel(const __half* __restrict__ qh,
                const __half* __restrict__ kh,
                const __half* __restrict__ vh,
                const float* __restrict__ Wout,
                const float* __restrict__ bias,
                float* __restrict__ outp)
{
    extern __shared__ __align__(1024) char smc[];
    const uint32_t sb = smem_u32(smc);

    const int tid  = threadIdx.x;
    const int w    = tid >> 5;       // 0..3, owns rows w*32..w*32+32
    const int lane = tid & 31;
    const int g    = lane >> 2;
    const int tg   = lane & 3;
    const int bh   = blockIdx.y;
    const int i0   = blockIdx.x << 7;

    const __half* Q  = qh + ((size_t)bh * 2048 + i0) * 128;
    const __half* Kg = kh + (size_t)bh * 2048 * 128;
    const __half* Vg = vh + (size_t)bh * 2048 * 128;

    // ---- stage Q: 128 rows, stride 272 B (overlays K buffers) ----
#pragma unroll
    for (int it = 0; it < 16; it++) {
        int idx = tid + (it << 7);
        int r = idx >> 4, c8 = idx & 15;
        uint4 v = *(const uint4*)&Q[r * 128 + (c8 << 3)];
        *(uint4*)(smc + r * 272 + (c8 << 4)) = v;
    }
    __syncthreads();

    // ---- Q A-frags ----
    uint32_t qf[8][2][4];
#pragma unroll
    for (int mt = 0; mt < 2; mt++) {
        const uint32_t abase = sb + ((w << 5) + (mt << 4) + (lane & 15)) * 272
                             + ((lane >> 4) << 4);
#pragma unroll
        for (int kt = 0; kt < 8; kt++)
            ldmx4(qf[kt][mt], abase + (kt << 5));
    }
    __syncthreads();   // Q staging region free

    // ---- mbarriers + prologue copies (tiles 0,1,2) ----
    if (tid == 0) {
#pragma unroll
        for (int b = 0; b < 3; b++)
            MBARRIER_INIT(sb + MB_ + (b << 3), 1);
    }
    __syncthreads();
    if (tid == 0) {
        FENCE_PROXY_ASYNC();
#pragma unroll
        for (int b = 0; b < 3; b++) {
            uint32_t mb = sb + MB_ + (b << 3);
            MBARRIER_EXPECT_TX(mb, 32768u);
            bulk_g2s(sb + KB_ + b * 16384, Kg + (size_t)b * 64 * 128, 16384u, mb);
            bulk_g2s(sb + VB_ + b * 16384, Vg + (size_t)b * 64 * 128, 16384u, mb);
        }
    }

    float o[2][16][4];
#pragma unroll
    for (int mt = 0; mt < 2; mt++)
#pragma unroll
        for (int nt = 0; nt < 16; nt++)
#pragma unroll
            for (int c = 0; c < 4; c++) o[mt][nt][c] = 0.f;
    float lacc[2][4];
#pragma unroll
    for (int mt = 0; mt < 2; mt++)
#pragma unroll
        for (int c = 0; c < 4; c++) lacc[mt][c] = 0.f;

    const int krow_l = ((lane >> 4) << 3) + (lane & 7);
    const int kch_l  = (lane >> 3) & 1;
    const int vrow_l = lane & 15;
    const int vch_l  = lane >> 4;
    const uint32_t ONES = 0x3C003C00u;    // half2(1,1)

    int bcur = 0, par = 0;
    for (int j = 0; j < 32; j++) {
        MBARRIER_WAIT_PARITY(sb + MB_ + (bcur << 3), par);

        const uint32_t kb = sb + KB_ + bcur * 16384;
        const uint32_t vb = sb + VB_ + bcur * 16384;

#pragma unroll
        for (int nh = 0; nh < 2; nh++) {
            float s[2][4][4];
#pragma unroll
            for (int mt = 0; mt < 2; mt++)
#pragma unroll
                for (int nt = 0; nt < 4; nt++)
#pragma unroll
                    for (int c = 0; c < 4; c++) s[mt][nt][c] = 0.f;

#pragma unroll
            for (int kt = 0; kt < 8; kt++) {
#pragma unroll
                for (int npl = 0; npl < 2; npl++) {
                    int row = (nh << 5) + (npl << 4) + krow_l;
                    int ch  = (kt << 1) + kch_l;
                    uint32_t b[4];
                    ldmx4(b, kb + row * 256 + (swz(ch, row) << 4));
#pragma unroll
                    for (int mt = 0; mt < 2; mt++) {
                        mma16h(s[mt][2 * npl],     qf[kt][mt], b[0], b[1]);
                        mma16h(s[mt][2 * npl + 1], qf[kt][mt], b[2], b[3]);
                    }
                }
            }

            uint32_t pf[2][2][4];   // [ktl][mt]
#pragma unroll
            for (int mt = 0; mt < 2; mt++)
#pragma unroll
                for (int nt = 0; nt < 4; nt++) {
                    uint32_t plo = ex2h2(f2h2(s[mt][nt][1], s[mt][nt][0]));
                    uint32_t phi = ex2h2(f2h2(s[mt][nt][3], s[mt][nt][2]));
                    pf[nt >> 1][mt][(nt & 1) << 1]       = plo;
                    pf[nt >> 1][mt][((nt & 1) << 1) + 1] = phi;
                }
#pragma unroll
            for (int mt = 0; mt < 2; mt++) {
                mma16h(lacc[mt], pf[0][mt], ONES, ONES);
                mma16h(lacc[mt], pf[1][mt], ONES, ONES);
            }

#pragma unroll
            for (int ktl = 0; ktl < 2; ktl++) {
#pragma unroll
                for (int np = 0; np < 8; np++) {
                    int row = (nh << 5) + (ktl << 4) + vrow_l;
                    int ch  = (np << 1) + vch_l;
                    uint32_t b[4];
                    ldmx4t(b, vb + row * 256 + (swz(ch, row) << 4));
#pragma unroll
                    for (int mt = 0; mt < 2; mt++) {
                        mma16h(o[mt][2 * np],     pf[ktl][mt], b[0], b[1]);
                        mma16h(o[mt][2 * np + 1], pf[ktl][mt], b[2], b[3]);
                    }
                }
            }
        }
        __syncthreads();   // all warps done with buffer bcur

        if (j < 29 && tid == 0) {
            uint32_t mb = sb + MB_ + (bcur << 3);
            MBARRIER_EXPECT_TX(mb, 32768u);
            bulk_g2s(sb + KB_ + bcur * 16384,
                     Kg + (size_t)(j + 3) * 64 * 128, 16384u, mb);
            bulk_g2s(sb + VB_ + bcur * 16384,
                     Vg + (size_t)(j + 3) * 64 * 128, 16384u, mb);
        }

        if (bcur == 2) { bcur = 0; par ^= 1; } else bcur++;
    }

    // ================= fused out-projection epilogue =================
    // Stage Wout (fp16 hi plane) into the dead K buffer region at offset 0.
#pragma unroll
    for (int it = 0; it < 32; it++) {
        int idx = tid + (it << 7);
        int r = idx >> 5, c = idx & 31;
        float4 vw = *(const float4*)&Wout[(size_t)r * 128 + (c << 2)];
        __half2 w01 = __floats2half2_rn(vw.x, vw.y);
        __half2 w23 = __floats2half2_rn(vw.z, vw.w);
        *(uint2*)(smc + r * 272 + (c << 3)) =
            make_uint2(*(uint32_t*)&w01, *(uint32_t*)&w23);
    }
    __syncthreads();

    const uint32_t wb4 = sb
        + (((lane >> 4) << 3) + (lane & 7)) * 272 + (((lane >> 3) & 1) << 4);

#pragma unroll
    for (int mt = 0; mt < 2; mt++) {
        const float inv0 = 1.f / lacc[mt][0];   // row g
        const float inv1 = 1.f / lacc[mt][2];   // row g+8

        // O C-frags -> fp16 A-frags (normalized). C layout == A layout.
        uint32_t af[8][4];
#pragma unroll
        for (int kt = 0; kt < 8; kt++) {
            af[kt][0] = f2h2(o[mt][2 * kt][1] * inv0,     o[mt][2 * kt][0] * inv0);
            af[kt][1] = f2h2(o[mt][2 * kt][3] * inv1,     o[mt][2 * kt][2] * inv1);
            af[kt][2] = f2h2(o[mt][2 * kt + 1][1] * inv0, o[mt][2 * kt + 1][0] * inv0);
            af[kt][3] = f2h2(o[mt][2 * kt + 1][3] * inv1, o[mt][2 * kt + 1][2] * inv1);
        }

        float oo[16][4];
#pragma unroll
        for (int nt = 0; nt < 16; nt++)
#pragma unroll
            for (int c = 0; c < 4; c++) oo[nt][c] = 0.f;

#pragma unroll
        for (int kt = 0; kt < 8; kt++)
#pragma unroll
            for (int ntp = 0; ntp < 8; ntp++) {
                uint32_t b[4];
                ldmx4(b, wb4 + ntp * 4352 + (kt << 5));
                mma16h(oo[2 * ntp],     af[kt], b[0], b[1]);
                mma16h(oo[2 * ntp + 1], af[kt], b[2], b[3]);
            }

        const size_t r0 = (size_t)bh * 2048 + i0 + (w << 5) + (mt << 4) + g;
        float* O0 = outp + r0 * 128;
        float* O1 = O0 + 8 * 128;
#pragma unroll
        for (int nt = 0; nt < 16; nt++) {
            const int col = (nt << 3) + (tg << 1);
            float b0 = __ldg(&bias[col]);
            float b1 = __ldg(&bias[col + 1]);
            *(float2*)&O0[col] = make_float2(oo[nt][0] + b0, oo[nt][1] + b1);
            *(float2*)&O1[col] = make_float2(oo[nt][2] + b0, oo[nt][3] + b1);
        }
    }
}

// ===========================================================================

extern "C" void kernel_launch(void* const* d_in, const int* in_sizes, int n_in,
                              void* d_out, int out_size)
{
    const float* q    = (const float*)d_in[0];
    const float* kv   = (const float*)d_in[1];
    const float* Wq   = (const float*)d_in[2];
    const float* Wkv  = (const float*)d_in[3];
    const float* Wout = (const float*)d_in[4];
    const float* bout = (const float*)d_in[5];
    float* out = (float*)d_out;

    __half *qhp, *khp, *vhp;
    cudaGetSymbolAddress((void**)&qhp, g_qh);
    cudaGetSymbolAddress((void**)&khp, g_kh);
    cudaGetSymbolAddress((void**)&vhp, g_vh);

    cudaFuncSetAttribute((const void*)proj_q_kernel,
                         cudaFuncAttributeMaxDynamicSharedMemorySize, 2 * PL);
    cudaFuncSetAttribute((const void*)proj_kv_kernel,
                         cudaFuncAttributeMaxDynamicSharedMemorySize, 3 * PL);
    cudaFuncSetAttribute((const void*)attn_mma_kernel,
                         cudaFuncAttributeMaxDynamicSharedMemorySize, ATT_BYTES);

    // q' = (q @ Wq^T) * QSCALE -> fp16 (unswizzled)
    proj_q_kernel<<<dim3(1, 1024), 256, 2 * PL>>>(q, Wq, qhp, QSCALE);
    // k' + v' in one kernel (kv staged once)
    proj_kv_kernel<<<dim3(1, 1024), 256, 3 * PL>>>(kv, Wkv, khp, vhp);
    // flash attention + fused out-projection (writes final fp32 output)
    attn_mma_kernel<<<dim3(16, 64), 128, ATT_BYTES>>>(
        qhp, khp, vhp, Wout, bout, out);
}

// round 16
// speedup vs baseline: 1.0091x; 1.0091x over previous
#include <cuda_runtime.h>
#include <cuda_fp16.h>
#include <cstdint>

#define ATT_SCALE 0.08838834764831845f            // 128^-0.5
#define QSCALE (0.08838834764831845f * 1.4426950408889634f)   // fold log2(e): exp -> exp2

// Scratch (allocation-free rule: __device__ globals)
__device__ __half g_qh [16777216];   // [64][2048][128] fp16 (pre-scaled by QSCALE)
__device__ __half g_kh [16777216];   // [64][2048][128] fp16, chunk-swizzled rows
__device__ __half g_vh [16777216];   // [64][2048][128] fp16, chunk-swizzled rows

// ===========================================================================
// helpers
// ===========================================================================
__device__ __forceinline__ uint32_t smem_u32(const void* p) {
    uint32_t a;
    asm("{ .reg .u64 t; cvta.to.shared.u64 t, %1; cvt.u32.u64 %0, t; }"
        : "=r"(a) : "l"(p));
    return a;
}
__device__ __forceinline__ void mma16h(float* d, const uint32_t* a,
                                       uint32_t b0, uint32_t b1) {
    asm volatile(
        "mma.sync.aligned.m16n8k16.row.col.f32.f16.f16.f32 "
        "{%0,%1,%2,%3}, {%4,%5,%6,%7}, {%8,%9}, {%0,%1,%2,%3};"
        : "+f"(d[0]), "+f"(d[1]), "+f"(d[2]), "+f"(d[3])
        : "r"(a[0]), "r"(a[1]), "r"(a[2]), "r"(a[3]), "r"(b0), "r"(b1));
}
__device__ __forceinline__ void ldmx2(uint32_t& b0, uint32_t& b1, uint32_t addr) {
    asm volatile("ldmatrix.sync.aligned.m8n8.x2.shared.b16 {%0,%1}, [%2];"
                 : "=r"(b0), "=r"(b1) : "r"(addr));
}
__device__ __forceinline__ void ldmx4(uint32_t* r, uint32_t addr) {
    asm volatile("ldmatrix.sync.aligned.m8n8.x4.shared.b16 {%0,%1,%2,%3}, [%4];"
                 : "=r"(r[0]), "=r"(r[1]), "=r"(r[2]), "=r"(r[3]) : "r"(addr));
}
__device__ __forceinline__ void ldmx4t(uint32_t* r, uint32_t addr) {
    asm volatile("ldmatrix.sync.aligned.m8n8.x4.trans.shared.b16 {%0,%1,%2,%3}, [%4];"
                 : "=r"(r[0]), "=r"(r[1]), "=r"(r[2]), "=r"(r[3]) : "r"(addr));
}
__device__ __forceinline__ uint32_t f2h2(float hi, float lo) {   // pack: lo in low half
    uint32_t r;
    asm("cvt.rn.f16x2.f32 %0, %1, %2;" : "=r"(r) : "f"(hi), "f"(lo));
    return r;
}
__device__ __forceinline__ uint32_t ex2h2(uint32_t x) {          // 2^x per half
    uint32_t r;
    asm("ex2.approx.f16x2 %0, %1;" : "=r"(r) : "r"(x));
    return r;
}
__device__ __forceinline__ void bulk_g2s(uint32_t dst, const void* src,
                                         uint32_t bytes, uint32_t mbar) {
    asm volatile(
        "cp.async.bulk.shared::cluster.global.mbarrier::complete_tx::bytes "
        "[%0], [%1], %2, [%3];"
        :: "r"(dst), "l"(src), "r"(bytes), "r"(mbar) : "memory");
}
#define MBARRIER_INIT(addr, cnt) \
    asm volatile("mbarrier.init.shared.b64 [%0], %1;" \
        :: "r"((uint32_t)(addr)), "r"((uint32_t)(cnt)) : "memory")
#define MBARRIER_EXPECT_TX(addr, tx) \
    asm volatile("mbarrier.arrive.expect_tx.shared.b64 _, [%0], %1;" \
        :: "r"((uint32_t)(addr)), "r"((uint32_t)(tx)) : "memory")
#define FENCE_PROXY_ASYNC() \
    asm volatile("fence.proxy.async.shared::cta;" ::: "memory")
#define MBARRIER_WAIT_PARITY(mbar_smem_addr, phase_parity) do { \
    uint32_t _mbar = (uint32_t)(mbar_smem_addr); \
    uint32_t _parity = (uint32_t)(phase_parity); \
    uint32_t _done; \
    asm volatile( \
        "{\n\t.reg .pred p;\n\t" \
        "mbarrier.try_wait.parity.shared.b64 p, [%1], %2;\n\t" \
        "selp.b32 %0, 1, 0, p;\n\t}" \
        : "=r"(_done) : "r"(_mbar), "r"(_parity) : "memory"); \
    if (!_done) { \
        asm volatile( \
            "{\n\t.reg .pred P1;\n\t" \
            "WAIT_LOOP_%=:\n\t" \
            "mbarrier.try_wait.parity.shared.b64 P1, [%0], %1, 0x989680;\n\t" \
            "@P1 bra.uni WAIT_DONE_%=;\n\t" \
            "bra.uni WAIT_LOOP_%=;\n\t" \
            "WAIT_DONE_%=:\n\t}" \
            :: "r"(_mbar), "r"(_parity) : "memory"); \
    } \
} while(0)

// chunk swizzle: 16B chunk c of row r -> (c&8) | ((c ^ (r&7)) & 7)
__device__ __forceinline__ int swz(int c, int r) {
    return (c & 8) | ((c ^ (r & 7)) & 7);
}

static constexpr int PL = 34816;   // smem plane: [128][136] halves

// ===========================================================================
// merged q + kv projection, one launch. blockIdx.z = 0: q path; 1: kv path.
//   q path : q' = (q @ Wq^T) * QSCALE -> qh (plain 1-mma, unswizzled)
//   kv path: stage kv A-tile once (hi/lo);
//            k' = A_hi @ Wk (1-mma) -> kh swizzled
//            v' = (A_hi+A_lo) @ Wv (2-mma) -> vh swizzled
// ===========================================================================
__global__ void __launch_bounds__(256, 2)
proj_qkv_kernel(const float* __restrict__ q, const float* __restrict__ kv,
                const float* __restrict__ Wq, const float* __restrict__ Wkv,
                __half* __restrict__ qh, __half* __restrict__ kh,
                __half* __restrict__ vh)
{
    extern __shared__ __align__(16) char smc[];
    const uint32_t sb = smem_u32(smc);

    const int tid  = threadIdx.x;
    const int w    = tid >> 5;
    const int lane = tid & 31;
    const int g    = lane >> 2;
    const int tg   = lane & 3;
    const int m0   = blockIdx.y << 7;
    const int r0   = m0 + (w << 4) + g;

    const uint32_t abase = sb + ((w << 4) + (lane & 15)) * 272
                         + ((lane >> 4) << 4);

    if (blockIdx.z == 0) {
        // ================= q path (planes: A @ 0, W @ PL) =================
#pragma unroll
        for (int it = 0; it < 16; it++) {
            int idx = tid + (it << 8);
            int r = idx >> 5, c = idx & 31;
            float4 va = *(const float4*)&q[(size_t)(m0 + r) * 128 + (c << 2)];
            __half2 a01 = __floats2half2_rn(va.x, va.y);
            __half2 a23 = __floats2half2_rn(va.z, va.w);
            *(uint2*)(smc + r * 272 + (c << 3)) =
                make_uint2(*(uint32_t*)&a01, *(uint32_t*)&a23);
            float4 vw = *(const float4*)&Wq[(size_t)r * 128 + (c << 2)];
            __half2 w01 = __floats2half2_rn(vw.x, vw.y);
            __half2 w23 = __floats2half2_rn(vw.z, vw.w);
            *(uint2*)(smc + PL + r * 272 + (c << 3)) =
                make_uint2(*(uint32_t*)&w01, *(uint32_t*)&w23);
        }
        __syncthreads();

        float o[16][4];
#pragma unroll
        for (int nt = 0; nt < 16; nt++)
#pragma unroll
            for (int c = 0; c < 4; c++) o[nt][c] = 0.f;

        const uint32_t bbase = sb + PL + (lane & 7) * 272
                             + (((lane >> 3) & 1) << 4);
#pragma unroll
        for (int kt = 0; kt < 8; kt++) {
            uint32_t ah[4];
            ldmx4(ah, abase + (kt << 5));
#pragma unroll
            for (int nt = 0; nt < 16; nt++) {
                uint32_t b0, b1;
                ldmx2(b0, b1, bbase + nt * 2176 + (kt << 5));
                mma16h(o[nt], ah, b0, b1);
            }
        }
#pragma unroll
        for (int nt = 0; nt < 16; nt++) {
            const int col = (nt << 3) + (tg << 1);
            *(__half2*)&qh[(size_t)r0 * 128 + col] =
                __floats2half2_rn(o[nt][0] * QSCALE, o[nt][1] * QSCALE);
            *(__half2*)&qh[(size_t)(r0 + 8) * 128 + col] =
                __floats2half2_rn(o[nt][2] * QSCALE, o[nt][3] * QSCALE);
        }
        return;
    }

    // ================= kv path (planes: A_hi @ 0, A_lo @ PL, W @ 2PL) ======
#pragma unroll
    for (int it = 0; it < 16; it++) {
        int idx = tid + (it << 8);
        int r = idx >> 5, c = idx & 31;
        float4 va = *(const float4*)&kv[(size_t)(m0 + r) * 128 + (c << 2)];
        __half2 a01 = __floats2half2_rn(va.x, va.y);
        __half2 a23 = __floats2half2_rn(va.z, va.w);
        *(uint2*)(smc + r * 272 + (c << 3)) =
            make_uint2(*(uint32_t*)&a01, *(uint32_t*)&a23);
        __half2 l01 = __floats2half2_rn(va.x - __low2float(a01),
                                        va.y - __high2float(a01));
        __half2 l23 = __floats2half2_rn(va.z - __low2float(a23),
                                        va.w - __high2float(a23));
        *(uint2*)(smc + PL + r * 272 + (c << 3)) =
            make_uint2(*(uint32_t*)&l01, *(uint32_t*)&l23);
        float4 vw = *(const float4*)&Wkv[(size_t)r * 128 + (c << 2)];
        __half2 w01 = __floats2half2_rn(vw.x, vw.y);
        __half2 w23 = __floats2half2_rn(vw.z, vw.w);
        *(uint2*)(smc + 2 * PL + r * 272 + (c << 3)) =
            make_uint2(*(uint32_t*)&w01, *(uint32_t*)&w23);
    }
    __syncthreads();

    const uint32_t bbase = sb + 2 * PL + (lane & 7) * 272
                         + (((lane >> 3) & 1) << 4);

    // ---- pass 1: k' (1-mma) ----
    {
        float o[16][4];
#pragma unroll
        for (int nt = 0; nt < 16; nt++)
#pragma unroll
            for (int c = 0; c < 4; c++) o[nt][c] = 0.f;
#pragma unroll
        for (int kt = 0; kt < 8; kt++) {
            uint32_t ah[4];
            ldmx4(ah, abase + (kt << 5));
#pragma unroll
            for (int nt = 0; nt < 16; nt++) {
                uint32_t b0, b1;
                ldmx2(b0, b1, bbase + nt * 2176 + (kt << 5));
                mma16h(o[nt], ah, b0, b1);
            }
        }
#pragma unroll
        for (int nt = 0; nt < 16; nt++) {
            const int col = (nt << 3) + (tg << 1);
            const int scol = (swz(col >> 3, r0) << 3) | (col & 7);
            *(__half2*)&kh[(size_t)r0 * 128 + scol] =
                __floats2half2_rn(o[nt][0], o[nt][1]);
            *(__half2*)&kh[(size_t)(r0 + 8) * 128 + scol] =
                __floats2half2_rn(o[nt][2], o[nt][3]);
        }
    }
    __syncthreads();

    // ---- restage W <- Wv ----
#pragma unroll
    for (int it = 0; it < 16; it++) {
        int idx = tid + (it << 8);
        int r = idx >> 5, c = idx & 31;
        float4 vw = *(const float4*)&Wkv[16384 + (size_t)r * 128 + (c << 2)];
        __half2 w01 = __floats2half2_rn(vw.x, vw.y);
        __half2 w23 = __floats2half2_rn(vw.z, vw.w);
        *(uint2*)(smc + 2 * PL + r * 272 + (c << 3)) =
            make_uint2(*(uint32_t*)&w01, *(uint32_t*)&w23);
    }
    __syncthreads();

    // ---- pass 2: v' (2-mma split) ----
    {
        float o[16][4];
#pragma unroll
        for (int nt = 0; nt < 16; nt++)
#pragma unroll
            for (int c = 0; c < 4; c++) o[nt][c] = 0.f;
#pragma unroll
        for (int kt = 0; kt < 8; kt++) {
            uint32_t ah[4], al[4];
            ldmx4(ah, abase + (kt << 5));
            ldmx4(al, abase + PL + (kt << 5));
#pragma unroll
            for (int nt = 0; nt < 16; nt++) {
                uint32_t b0, b1;
                ldmx2(b0, b1, bbase + nt * 2176 + (kt << 5));
                mma16h(o[nt], ah, b0, b1);
                mma16h(o[nt], al, b0, b1);
            }
        }
#pragma unroll
        for (int nt = 0; nt < 16; nt++) {
            const int col = (nt << 3) + (tg << 1);
            const int scol = (swz(col >> 3, r0) << 3) | (col & 7);
            *(__half2*)&vh[(size_t)r0 * 128 + scol] =
                __floats2half2_rn(o[nt][0], o[nt][1]);
            *(__half2*)&vh[(size_t)(r0 + 8) * 128 + scol] =
                __floats2half2_rn(o[nt][2], o[nt][3]);
        }
    }
}

// ===========================================================================
// flash attention + fused out-projection (R13-exact: 2-deep bulk pipeline,
// per-tile syncthreads, fused Wout epilogue).
// ===========================================================================
static constexpr int KB_  = 0;        // K bufs: 2 x 16384 (reused for Wout at end)
static constexpr int VB_  = 32768;    // V bufs: 2 x 16384
static constexpr int MB_  = 65536;    // 2 mbarriers
static constexpr int ATT_BYTES = 65552;

__global__ void __launch_bounds__(128, 2)
attn_mma_kernel(const __half* __restrict__ qh,
                const __half* __restrict__ kh,
                const __half* __restrict__ vh,
                const float* __restrict__ Wout,
                const float* __restrict__ bias,
                float* __restrict__ outp)
{
    extern __shared__ __align__(1024) char smc[];
    const uint32_t sb = smem_u32(smc);

    const int tid  = threadIdx.x;
    const int w    = tid >> 5;       // 0..3, owns rows w*32..w*32+32
    const int lane = tid & 31;
    const int g    = lane >> 2;
    const int tg   = lane & 3;
    const int bh   = blockIdx.y;
    const int i0   = blockIdx.x << 7;

    const __half* Q  = qh + ((size_t)bh * 2048 + i0) * 128;
    const __half* Kg = kh + (size_t)bh * 2048 * 128;
    const __half* Vg = vh + (size_t)bh * 2048 * 128;

    // ---- stage Q: 128 rows, stride 272 B ----
#pragma unroll
    for (int it = 0; it < 16; it++) {
        int idx = tid + (it << 7);
        int r = idx >> 4, c8 = idx & 15;
        uint4 v = *(const uint4*)&Q[r * 128 + (c8 << 3)];
        *(uint4*)(smc + r * 272 + (c8 << 4)) = v;
    }
    __syncthreads();

    // ---- Q A-frags ----
    uint32_t qf[8][2][4];
#pragma unroll
    for (int mt = 0; mt < 2; mt++) {
        const uint32_t abase = sb + ((w << 5) + (mt << 4) + (lane & 15)) * 272
                             + ((lane >> 4) << 4);
#pragma unroll
        for (int kt = 0; kt < 8; kt++)
            ldmx4(qf[kt][mt], abase + (kt << 5));
    }
    __syncthreads();   // Q staging region free (K buffers overlay it)

    // ---- mbarriers + prologue copies ----
    if (tid == 0) {
        MBARRIER_INIT(sb + MB_,     1);
        MBARRIER_INIT(sb + MB_ + 8, 1);
    }
    __syncthreads();
    if (tid == 0) {
        FENCE_PROXY_ASYNC();
#pragma unroll
        for (int b = 0; b < 2; b++) {
            uint32_t mb = sb + MB_ + (b << 3);
            MBARRIER_EXPECT_TX(mb, 32768u);
            bulk_g2s(sb + KB_ + (b << 14), Kg + (size_t)b * 64 * 128, 16384u, mb);
            bulk_g2s(sb + VB_ + (b << 14), Vg + (size_t)b * 64 * 128, 16384u, mb);
        }
    }

    float o[2][16][4];
#pragma unroll
    for (int mt = 0; mt < 2; mt++)
#pragma unroll
        for (int nt = 0; nt < 16; nt++)
#pragma unroll
            for (int c = 0; c < 4; c++) o[mt][nt][c] = 0.f;
    float lacc[2][4];
#pragma unroll
    for (int mt = 0; mt < 2; mt++)
#pragma unroll
        for (int c = 0; c < 4; c++) lacc[mt][c] = 0.f;

    const int krow_l = ((lane >> 4) << 3) + (lane & 7);
    const int kch_l  = (lane >> 3) & 1;
    const int vrow_l = lane & 15;
    const int vch_l  = lane >> 4;
    const uint32_t ONES = 0x3C003C00u;    // half2(1,1)

    for (int j = 0; j < 32; j++) {
        MBARRIER_WAIT_PARITY(sb + MB_ + ((j & 1) << 3), (j >> 1) & 1);

        const uint32_t kb = sb + KB_ + ((j & 1) << 14);
        const uint32_t vb = sb + VB_ + ((j & 1) << 14);

#pragma unroll
        for (int nh = 0; nh < 2; nh++) {
            float s[2][4][4];
#pragma unroll
            for (int mt = 0; mt < 2; mt++)
#pragma unroll
                for (int nt = 0; nt < 4; nt++)
#pragma unroll
                    for (int c = 0; c < 4; c++) s[mt][nt][c] = 0.f;

#pragma unroll
            for (int kt = 0; kt < 8; kt++) {
#pragma unroll
                for (int npl = 0; npl < 2; npl++) {
                    int row = (nh << 5) + (npl << 4) + krow_l;
                    int ch  = (kt << 1) + kch_l;
                    uint32_t b[4];
                    ldmx4(b, kb + row * 256 + (swz(ch, row) << 4));
#pragma unroll
                    for (int mt = 0; mt < 2; mt++) {
                        mma16h(s[mt][2 * npl],     qf[kt][mt], b[0], b[1]);
                        mma16h(s[mt][2 * npl + 1], qf[kt][mt], b[2], b[3]);
                    }
                }
            }

            uint32_t pf[2][2][4];   // [ktl][mt]
#pragma unroll
            for (int mt = 0; mt < 2; mt++)
#pragma unroll
                for (int nt = 0; nt < 4; nt++) {
                    uint32_t plo = ex2h2(f2h2(s[mt][nt][1], s[mt][nt][0]));
                    uint32_t phi = ex2h2(f2h2(s[mt][nt][3], s[mt][nt][2]));
                    pf[nt >> 1][mt][(nt & 1) << 1]       = plo;
                    pf[nt >> 1][mt][((nt & 1) << 1) + 1] = phi;
                }
#pragma unroll
            for (int mt = 0; mt < 2; mt++) {
                mma16h(lacc[mt], pf[0][mt], ONES, ONES);
                mma16h(lacc[mt], pf[1][mt], ONES, ONES);
            }

#pragma unroll
            for (int ktl = 0; ktl < 2; ktl++) {
#pragma unroll
                for (int np = 0; np < 8; np++) {
                    int row = (nh << 5) + (ktl << 4) + vrow_l;
                    int ch  = (np << 1) + vch_l;
                    uint32_t b[4];
                    ldmx4t(b, vb + row * 256 + (swz(ch, row) << 4));
#pragma unroll
                    for (int mt = 0; mt < 2; mt++) {
                        mma16h(o[mt][2 * np],     pf[ktl][mt], b[0], b[1]);
                        mma16h(o[mt][2 * np + 1], pf[ktl][mt], b[2], b[3]);
                    }
                }
            }
        }
        __syncthreads();

        if (j < 30 && tid == 0) {
            uint32_t mb = sb + MB_ + ((j & 1) << 3);
            MBARRIER_EXPECT_TX(mb, 32768u);
            bulk_g2s(sb + KB_ + ((j & 1) << 14),
                     Kg + (size_t)(j + 2) * 64 * 128, 16384u, mb);
            bulk_g2s(sb + VB_ + ((j & 1) << 14),
                     Vg + (size_t)(j + 2) * 64 * 128, 16384u, mb);
        }
    }

    // ================= fused out-projection epilogue =================
#pragma unroll
    for (int it = 0; it < 32; it++) {
        int idx = tid + (it << 7);
        int r = idx >> 5, c = idx & 31;
        float4 vw = *(const float4*)&Wout[(size_t)r * 128 + (c << 2)];
        __half2 w01 = __floats2half2_rn(vw.x, vw.y);
        __half2 w23 = __floats2half2_rn(vw.z, vw.w);
        *(uint2*)(smc + r * 272 + (c << 3)) =
            make_uint2(*(uint32_t*)&w01, *(uint32_t*)&w23);
    }
    __syncthreads();

    const uint32_t wb = sb + (lane & 7) * 272 + (((lane >> 3) & 1) << 4);

#pragma unroll
    for (int mt = 0; mt < 2; mt++) {
        const float inv0 = 1.f / lacc[mt][0];   // row g
        const float inv1 = 1.f / lacc[mt][2];   // row g+8

        uint32_t af[8][4];
#pragma unroll
        for (int kt = 0; kt < 8; kt++) {
            af[kt][0] = f2h2(o[mt][2 * kt][1] * inv0,     o[mt][2 * kt][0] * inv0);
            af[kt][1] = f2h2(o[mt][2 * kt][3] * inv1,     o[mt][2 * kt][2] * inv1);
            af[kt][2] = f2h2(o[mt][2 * kt + 1][1] * inv0, o[mt][2 * kt + 1][0] * inv0);
            af[kt][3] = f2h2(o[mt][2 * kt + 1][3] * inv1, o[mt][2 * kt + 1][2] * inv1);
        }

        float oo[16][4];
#pragma unroll
        for (int nt = 0; nt < 16; nt++)
#pragma unroll
            for (int c = 0; c < 4; c++) oo[nt][c] = 0.f;

#pragma unroll
        for (int kt = 0; kt < 8; kt++)
#pragma unroll
            for (int nt = 0; nt < 16; nt++) {
                uint32_t b0, b1;
                ldmx2(b0, b1, wb + nt * 2176 + (kt << 5));
                mma16h(oo[nt], af[kt], b0, b1);
            }

        const size_t r0 = (size_t)bh * 2048 + i0 + (w << 5) + (mt << 4) + g;
        float* O0 = outp + r0 * 128;
        float* O1 = O0 + 8 * 128;
#pragma unroll
        for (int nt = 0; nt < 16; nt++) {
            const int col = (nt << 3) + (tg << 1);
            float b0 = __ldg(&bias[col]);
            float b1 = __ldg(&bias[col + 1]);
            *(float2*)&O0[col] = make_float2(oo[nt][0] + b0, oo[nt][1] + b1);
            *(float2*)&O1[col] = make_float2(oo[nt][2] + b0, oo[nt][3] + b1);
        }
    }
}

// ===========================================================================

extern "C" void kernel_launch(void* const* d_in, const int* in_sizes, int n_in,
                              void* d_out, int out_size)
{
    const float* q    = (const float*)d_in[0];
    const float* kv   = (const float*)d_in[1];
    const float* Wq   = (const float*)d_in[2];
    const float* Wkv  = (const float*)d_in[3];
    const float* Wout = (const float*)d_in[4];
    const float* bout = (const float*)d_in[5];
    float* out = (float*)d_out;

    __half *qhp, *khp, *vhp;
    cudaGetSymbolAddress((void**)&qhp, g_qh);
    cudaGetSymbolAddress((void**)&khp, g_kh);
    cudaGetSymbolAddress((void**)&vhp, g_vh);

    cudaFuncSetAttribute((const void*)proj_qkv_kernel,
                         cudaFuncAttributeMaxDynamicSharedMemorySize, 3 * PL);
    cudaFuncSetAttribute((const void*)attn_mma_kernel,
                         cudaFuncAttributeMaxDynamicSharedMemorySize, ATT_BYTES);

    // q' / k' / v' in one launch (z=0: q path, z=1: kv path)
    proj_qkv_kernel<<<dim3(1, 1024, 2), 256, 3 * PL>>>(
        q, kv, Wq, Wkv, qhp, khp, vhp);
    // flash attention + fused out-projection (writes final fp32 output)
    attn_mma_kernel<<<dim3(16, 64), 128, ATT_BYTES>>>(
        qhp, khp, vhp, Wout, bout, out);
}

// round 17
// speedup vs baseline: 1.0368x; 1.0275x over previous
#include <cuda_runtime.h>
#include <cuda_fp16.h>
#include <cstdint>

#define ATT_SCALE 0.08838834764831845f            // 128^-0.5
#define QSCALE (0.08838834764831845f * 1.4426950408889634f)   // fold log2(e): exp -> exp2

// Scratch (allocation-free rule: __device__ globals)
__device__ __half g_qh [16777216];   // [64][2048][128] fp16 (pre-scaled by QSCALE)
__device__ __half g_kh [16777216];   // [64][2048][128] fp16, chunk-swizzled rows
__device__ __half g_vh [16777216];   // [64][2048][128] fp16, chunk-swizzled rows
__device__ __align__(16) __half g_wh[17408];   // Wout fp16, [128][136] layout

// ===========================================================================
// helpers
// ===========================================================================
__device__ __forceinline__ uint32_t smem_u32(const void* p) {
    uint32_t a;
    asm("{ .reg .u64 t; cvta.to.shared.u64 t, %1; cvt.u32.u64 %0, t; }"
        : "=r"(a) : "l"(p));
    return a;
}
__device__ __forceinline__ void mma16h(float* d, const uint32_t* a,
                                       uint32_t b0, uint32_t b1) {
    asm volatile(
        "mma.sync.aligned.m16n8k16.row.col.f32.f16.f16.f32 "
        "{%0,%1,%2,%3}, {%4,%5,%6,%7}, {%8,%9}, {%0,%1,%2,%3};"
        : "+f"(d[0]), "+f"(d[1]), "+f"(d[2]), "+f"(d[3])
        : "r"(a[0]), "r"(a[1]), "r"(a[2]), "r"(a[3]), "r"(b0), "r"(b1));
}
__device__ __forceinline__ void ldmx2(uint32_t& b0, uint32_t& b1, uint32_t addr) {
    asm volatile("ldmatrix.sync.aligned.m8n8.x2.shared.b16 {%0,%1}, [%2];"
                 : "=r"(b0), "=r"(b1) : "r"(addr));
}
__device__ __forceinline__ void ldmx4(uint32_t* r, uint32_t addr) {
    asm volatile("ldmatrix.sync.aligned.m8n8.x4.shared.b16 {%0,%1,%2,%3}, [%4];"
                 : "=r"(r[0]), "=r"(r[1]), "=r"(r[2]), "=r"(r[3]) : "r"(addr));
}
__device__ __forceinline__ void ldmx4t(uint32_t* r, uint32_t addr) {
    asm volatile("ldmatrix.sync.aligned.m8n8.x4.trans.shared.b16 {%0,%1,%2,%3}, [%4];"
                 : "=r"(r[0]), "=r"(r[1]), "=r"(r[2]), "=r"(r[3]) : "r"(addr));
}
__device__ __forceinline__ uint32_t f2h2(float hi, float lo) {   // pack: lo in low half
    uint32_t r;
    asm("cvt.rn.f16x2.f32 %0, %1, %2;" : "=r"(r) : "f"(hi), "f"(lo));
    return r;
}
__device__ __forceinline__ uint32_t ex2h2(uint32_t x) {          // 2^x per half
    uint32_t r;
    asm("ex2.approx.f16x2 %0, %1;" : "=r"(r) : "r"(x));
    return r;
}
__device__ __forceinline__ void bulk_g2s(uint32_t dst, const void* src,
                                         uint32_t bytes, uint32_t mbar) {
    asm volatile(
        "cp.async.bulk.shared::cluster.global.mbarrier::complete_tx::bytes "
        "[%0], [%1], %2, [%3];"
        :: "r"(dst), "l"(src), "r"(bytes), "r"(mbar) : "memory");
}
#define MBARRIER_INIT(addr, cnt) \
    asm volatile("mbarrier.init.shared.b64 [%0], %1;" \
        :: "r"((uint32_t)(addr)), "r"((uint32_t)(cnt)) : "memory")
#define MBARRIER_EXPECT_TX(addr, tx) \
    asm volatile("mbarrier.arrive.expect_tx.shared.b64 _, [%0], %1;" \
        :: "r"((uint32_t)(addr)), "r"((uint32_t)(tx)) : "memory")
#define FENCE_PROXY_ASYNC() \
    asm volatile("fence.proxy.async.shared::cta;" ::: "memory")
#define MBARRIER_WAIT_PARITY(mbar_smem_addr, phase_parity) do { \
    uint32_t _mbar = (uint32_t)(mbar_smem_addr); \
    uint32_t _parity = (uint32_t)(phase_parity); \
    uint32_t _done; \
    asm volatile( \
        "{\n\t.reg .pred p;\n\t" \
        "mbarrier.try_wait.parity.shared.b64 p, [%1], %2;\n\t" \
        "selp.b32 %0, 1, 0, p;\n\t}" \
        : "=r"(_done) : "r"(_mbar), "r"(_parity) : "memory"); \
    if (!_done) { \
        asm volatile( \
            "{\n\t.reg .pred P1;\n\t" \
            "WAIT_LOOP_%=:\n\t" \
            "mbarrier.try_wait.parity.shared.b64 P1, [%0], %1, 0x989680;\n\t" \
            "@P1 bra.uni WAIT_DONE_%=;\n\t" \
            "bra.uni WAIT_LOOP_%=;\n\t" \
            "WAIT_DONE_%=:\n\t}" \
            :: "r"(_mbar), "r"(_parity) : "memory"); \
    } \
} while(0)

// chunk swizzle: 16B chunk c of row r -> (c&8) | ((c ^ (r&7)) & 7)
__device__ __forceinline__ int swz(int c, int r) {
    return (c & 8) | ((c ^ (r & 7)) & 7);
}

static constexpr int PL = 34816;   // smem plane: [128][136] halves

// ===========================================================================
// q projection: plain fp16 1-mma, fp16 out (unswizzled), *QSCALE.
//   CTA y==0 additionally converts Wout -> g_wh ([128][136] fp16 layout).
// ===========================================================================
__global__ void __launch_bounds__(256, 2)
proj_q_kernel(const float* __restrict__ A,
              const float* __restrict__ W,
              const float* __restrict__ Wout,
              __half* __restrict__ Ch, __half* __restrict__ wh)
{
    extern __shared__ __align__(16) char smc[];
    const uint32_t sb = smem_u32(smc);

    const int tid  = threadIdx.x;
    const int w    = tid >> 5;
    const int lane = tid & 31;
    const int g    = lane >> 2;
    const int tg   = lane & 3;
    const int m0   = blockIdx.y << 7;

#pragma unroll
    for (int it = 0; it < 16; it++) {
        int idx = tid + (it << 8);
        int r = idx >> 5, c = idx & 31;
        float4 va = *(const float4*)&A[(size_t)(m0 + r) * 128 + (c << 2)];
        __half2 a01 = __floats2half2_rn(va.x, va.y);
        __half2 a23 = __floats2half2_rn(va.z, va.w);
        *(uint2*)(smc + r * 272 + (c << 3)) =
            make_uint2(*(uint32_t*)&a01, *(uint32_t*)&a23);
        float4 vw = *(const float4*)&W[(size_t)r * 128 + (c << 2)];
        __half2 w01 = __floats2half2_rn(vw.x, vw.y);
        __half2 w23 = __floats2half2_rn(vw.z, vw.w);
        *(uint2*)(smc + PL + r * 272 + (c << 3)) =
            make_uint2(*(uint32_t*)&w01, *(uint32_t*)&w23);
    }
    // CTA 0: pre-convert Wout into g_wh ([128][136] halves, stride 272B)
    if (blockIdx.y == 0) {
#pragma unroll
        for (int it = 0; it < 16; it++) {
            int idx = tid + (it << 8);
            int r = idx >> 5, c = idx & 31;
            float4 vw = *(const float4*)&Wout[(size_t)r * 128 + (c << 2)];
            __half2 w01 = __floats2half2_rn(vw.x, vw.y);
            __half2 w23 = __floats2half2_rn(vw.z, vw.w);
            *(uint2*)&wh[r * 136 + (c << 2)] =
                make_uint2(*(uint32_t*)&w01, *(uint32_t*)&w23);
        }
    }
    __syncthreads();

    float o[16][4];
#pragma unroll
    for (int nt = 0; nt < 16; nt++)
#pragma unroll
        for (int c = 0; c < 4; c++) o[nt][c] = 0.f;

    const uint32_t abase = sb + ((w << 4) + (lane & 15)) * 272
                         + ((lane >> 4) << 4);
    const uint32_t bbase = sb + PL + (lane & 7) * 272
                         + (((lane >> 3) & 1) << 4);

#pragma unroll
    for (int kt = 0; kt < 8; kt++) {
        uint32_t ah[4];
        ldmx4(ah, abase + (kt << 5));
#pragma unroll
        for (int nt = 0; nt < 16; nt++) {
            uint32_t b0, b1;
            ldmx2(b0, b1, bbase + nt * 2176 + (kt << 5));
            mma16h(o[nt], ah, b0, b1);
        }
    }

    const int r0 = m0 + (w << 4) + g;
#pragma unroll
    for (int nt = 0; nt < 16; nt++) {
        const int col = (nt << 3) + (tg << 1);
        *(__half2*)&Ch[(size_t)r0 * 128 + col] =
            __floats2half2_rn(o[nt][0] * QSCALE, o[nt][1] * QSCALE);
        *(__half2*)&Ch[(size_t)(r0 + 8) * 128 + col] =
            __floats2half2_rn(o[nt][2] * QSCALE, o[nt][3] * QSCALE);
    }
}

// ===========================================================================
// merged k+v projection: stage kv A-tile ONCE (hi/lo), two W passes.
// ===========================================================================
__global__ void __launch_bounds__(256, 2)
proj_kv_kernel(const float* __restrict__ A,
               const float* __restrict__ Wkv,
               __half* __restrict__ kh, __half* __restrict__ vh)
{
    extern __shared__ __align__(16) char smc[];
    const uint32_t sb = smem_u32(smc);
    // planes: A_hi @ 0, A_lo @ PL, W @ 2*PL

    const int tid  = threadIdx.x;
    const int w    = tid >> 5;
    const int lane = tid & 31;
    const int g    = lane >> 2;
    const int tg   = lane & 3;
    const int m0   = blockIdx.y << 7;

#pragma unroll
    for (int it = 0; it < 16; it++) {
        int idx = tid + (it << 8);
        int r = idx >> 5, c = idx & 31;
        float4 va = *(const float4*)&A[(size_t)(m0 + r) * 128 + (c << 2)];
        __half2 a01 = __floats2half2_rn(va.x, va.y);
        __half2 a23 = __floats2half2_rn(va.z, va.w);
        *(uint2*)(smc + r * 272 + (c << 3)) =
            make_uint2(*(uint32_t*)&a01, *(uint32_t*)&a23);
        __half2 l01 = __floats2half2_rn(va.x - __low2float(a01),
                                        va.y - __high2float(a01));
        __half2 l23 = __floats2half2_rn(va.z - __low2float(a23),
                                        va.w - __high2float(a23));
        *(uint2*)(smc + PL + r * 272 + (c << 3)) =
            make_uint2(*(uint32_t*)&l01, *(uint32_t*)&l23);
        float4 vw = *(const float4*)&Wkv[(size_t)r * 128 + (c << 2)];
        __half2 w01 = __floats2half2_rn(vw.x, vw.y);
        __half2 w23 = __floats2half2_rn(vw.z, vw.w);
        *(uint2*)(smc + 2 * PL + r * 272 + (c << 3)) =
            make_uint2(*(uint32_t*)&w01, *(uint32_t*)&w23);
    }
    __syncthreads();

    const uint32_t abase = sb + ((w << 4) + (lane & 15)) * 272
                         + ((lane >> 4) << 4);
    const uint32_t bbase = sb + 2 * PL + (lane & 7) * 272
                         + (((lane >> 3) & 1) << 4);
    const int r0 = m0 + (w << 4) + g;

    // ---- pass 1: k' (1-mma) ----
    {
        float o[16][4];
#pragma unroll
        for (int nt = 0; nt < 16; nt++)
#pragma unroll
            for (int c = 0; c < 4; c++) o[nt][c] = 0.f;
#pragma unroll
        for (int kt = 0; kt < 8; kt++) {
            uint32_t ah[4];
            ldmx4(ah, abase + (kt << 5));
#pragma unroll
            for (int nt = 0; nt < 16; nt++) {
                uint32_t b0, b1;
                ldmx2(b0, b1, bbase + nt * 2176 + (kt << 5));
                mma16h(o[nt], ah, b0, b1);
            }
        }
#pragma unroll
        for (int nt = 0; nt < 16; nt++) {
            const int col = (nt << 3) + (tg << 1);
            const int scol = (swz(col >> 3, r0) << 3) | (col & 7);
            *(__half2*)&kh[(size_t)r0 * 128 + scol] =
                __floats2half2_rn(o[nt][0], o[nt][1]);
            *(__half2*)&kh[(size_t)(r0 + 8) * 128 + scol] =
                __floats2half2_rn(o[nt][2], o[nt][3]);
        }
    }
    __syncthreads();

    // ---- restage W <- Wv ----
#pragma unroll
    for (int it = 0; it < 16; it++) {
        int idx = tid + (it << 8);
        int r = idx >> 5, c = idx & 31;
        float4 vw = *(const float4*)&Wkv[16384 + (size_t)r * 128 + (c << 2)];
        __half2 w01 = __floats2half2_rn(vw.x, vw.y);
        __half2 w23 = __floats2half2_rn(vw.z, vw.w);
        *(uint2*)(smc + 2 * PL + r * 272 + (c << 3)) =
            make_uint2(*(uint32_t*)&w01, *(uint32_t*)&w23);
    }
    __syncthreads();

    // ---- pass 2: v' (2-mma split) ----
    {
        float o[16][4];
#pragma unroll
        for (int nt = 0; nt < 16; nt++)
#pragma unroll
            for (int c = 0; c < 4; c++) o[nt][c] = 0.f;
#pragma unroll
        for (int kt = 0; kt < 8; kt++) {
            uint32_t ah[4], al[4];
            ldmx4(ah, abase + (kt << 5));
            ldmx4(al, abase + PL + (kt << 5));
#pragma unroll
            for (int nt = 0; nt < 16; nt++) {
                uint32_t b0, b1;
                ldmx2(b0, b1, bbase + nt * 2176 + (kt << 5));
                mma16h(o[nt], ah, b0, b1);
                mma16h(o[nt], al, b0, b1);
            }
        }
#pragma unroll
        for (int nt = 0; nt < 16; nt++) {
            const int col = (nt << 3) + (tg << 1);
            const int scol = (swz(col >> 3, r0) << 3) | (col & 7);
            *(__half2*)&vh[(size_t)r0 * 128 + scol] =
                __floats2half2_rn(o[nt][0], o[nt][1]);
            *(__half2*)&vh[(size_t)(r0 + 8) * 128 + scol] =
                __floats2half2_rn(o[nt][2], o[nt][3]);
        }
    }
}

// ===========================================================================
// flash attention + fused out-projection (R13 loop). Wout is prefetched by a
// third bulk copy in the prologue into a dedicated region; the epilogue just
// waits its mbarrier (no LDG/convert/STS on the critical path) and uses
// ldmx4 B-frags.
// ===========================================================================
static constexpr int KB_  = 0;        // K bufs: 2 x 16384
static constexpr int VB_  = 32768;    // V bufs: 2 x 16384
static constexpr int MB_  = 65536;    // 3 mbarriers (24 B)
static constexpr int WB_  = 65568;    // Wout fp16 [128][136]: 34816 B
static constexpr int ATT_BYTES = WB_ + 34816;   // 100384

__global__ void __launch_bounds__(128, 2)
attn_mma_kernel(const __half* __restrict__ qh,
                const __half* __restrict__ kh,
                const __half* __restrict__ vh,
                const __half* __restrict__ wh,
                const float* __restrict__ bias,
                float* __restrict__ outp)
{
    extern __shared__ __align__(1024) char smc[];
    const uint32_t sb = smem_u32(smc);

    const int tid  = threadIdx.x;
    const int w    = tid >> 5;       // 0..3, owns rows w*32..w*32+32
    const int lane = tid & 31;
    const int g    = lane >> 2;
    const int tg   = lane & 3;
    const int bh   = blockIdx.y;
    const int i0   = blockIdx.x << 7;

    const __half* Q  = qh + ((size_t)bh * 2048 + i0) * 128;
    const __half* Kg = kh + (size_t)bh * 2048 * 128;
    const __half* Vg = vh + (size_t)bh * 2048 * 128;

    // ---- stage Q: 128 rows, stride 272 B (overlays K buffers) ----
#pragma unroll
    for (int it = 0; it < 16; it++) {
        int idx = tid + (it << 7);
        int r = idx >> 4, c8 = idx & 15;
        uint4 v = *(const uint4*)&Q[r * 128 + (c8 << 3)];
        *(uint4*)(smc + r * 272 + (c8 << 4)) = v;
    }
    __syncthreads();

    // ---- Q A-frags ----
    uint32_t qf[8][2][4];
#pragma unroll
    for (int mt = 0; mt < 2; mt++) {
        const uint32_t abase = sb + ((w << 5) + (mt << 4) + (lane & 15)) * 272
                             + ((lane >> 4) << 4);
#pragma unroll
        for (int kt = 0; kt < 8; kt++)
            ldmx4(qf[kt][mt], abase + (kt << 5));
    }
    __syncthreads();   // Q staging region free (K buffers overlay it)

    // ---- mbarriers + prologue copies (K/V tiles 0,1 + Wout) ----
    if (tid == 0) {
        MBARRIER_INIT(sb + MB_,      1);
        MBARRIER_INIT(sb + MB_ + 8,  1);
        MBARRIER_INIT(sb + MB_ + 16, 1);
    }
    __syncthreads();
    if (tid == 0) {
        FENCE_PROXY_ASYNC();
#pragma unroll
        for (int b = 0; b < 2; b++) {
            uint32_t mb = sb + MB_ + (b << 3);
            MBARRIER_EXPECT_TX(mb, 32768u);
            bulk_g2s(sb + KB_ + (b << 14), Kg + (size_t)b * 64 * 128, 16384u, mb);
            bulk_g2s(sb + VB_ + (b << 14), Vg + (size_t)b * 64 * 128, 16384u, mb);
        }
        MBARRIER_EXPECT_TX(sb + MB_ + 16, 34816u);
        bulk_g2s(sb + WB_, wh, 34816u, sb + MB_ + 16);
    }

    float o[2][16][4];
#pragma unroll
    for (int mt = 0; mt < 2; mt++)
#pragma unroll
        for (int nt = 0; nt < 16; nt++)
#pragma unroll
            for (int c = 0; c < 4; c++) o[mt][nt][c] = 0.f;
    float lacc[2][4];
#pragma unroll
    for (int mt = 0; mt < 2; mt++)
#pragma unroll
        for (int c = 0; c < 4; c++) lacc[mt][c] = 0.f;

    const int krow_l = ((lane >> 4) << 3) + (lane & 7);
    const int kch_l  = (lane >> 3) & 1;
    const int vrow_l = lane & 15;
    const int vch_l  = lane >> 4;
    const uint32_t ONES = 0x3C003C00u;    // half2(1,1)

    for (int j = 0; j < 32; j++) {
        MBARRIER_WAIT_PARITY(sb + MB_ + ((j & 1) << 3), (j >> 1) & 1);

        const uint32_t kb = sb + KB_ + ((j & 1) << 14);
        const uint32_t vb = sb + VB_ + ((j & 1) << 14);

#pragma unroll
        for (int nh = 0; nh < 2; nh++) {
            float s[2][4][4];
#pragma unroll
            for (int mt = 0; mt < 2; mt++)
#pragma unroll
                for (int nt = 0; nt < 4; nt++)
#pragma unroll
                    for (int c = 0; c < 4; c++) s[mt][nt][c] = 0.f;

#pragma unroll
            for (int kt = 0; kt < 8; kt++) {
#pragma unroll
                for (int npl = 0; npl < 2; npl++) {
                    int row = (nh << 5) + (npl << 4) + krow_l;
                    int ch  = (kt << 1) + kch_l;
                    uint32_t b[4];
                    ldmx4(b, kb + row * 256 + (swz(ch, row) << 4));
#pragma unroll
                    for (int mt = 0; mt < 2; mt++) {
                        mma16h(s[mt][2 * npl],     qf[kt][mt], b[0], b[1]);
                        mma16h(s[mt][2 * npl + 1], qf[kt][mt], b[2], b[3]);
                    }
                }
            }

            uint32_t pf[2][2][4];   // [ktl][mt]
#pragma unroll
            for (int mt = 0; mt < 2; mt++)
#pragma unroll
                for (int nt = 0; nt < 4; nt++) {
                    uint32_t plo = ex2h2(f2h2(s[mt][nt][1], s[mt][nt][0]));
                    uint32_t phi = ex2h2(f2h2(s[mt][nt][3], s[mt][nt][2]));
                    pf[nt >> 1][mt][(nt & 1) << 1]       = plo;
                    pf[nt >> 1][mt][((nt & 1) << 1) + 1] = phi;
                }
#pragma unroll
            for (int mt = 0; mt < 2; mt++) {
                mma16h(lacc[mt], pf[0][mt], ONES, ONES);
                mma16h(lacc[mt], pf[1][mt], ONES, ONES);
            }

#pragma unroll
            for (int ktl = 0; ktl < 2; ktl++) {
#pragma unroll
                for (int np = 0; np < 8; np++) {
                    int row = (nh << 5) + (ktl << 4) + vrow_l;
                    int ch  = (np << 1) + vch_l;
                    uint32_t b[4];
                    ldmx4t(b, vb + row * 256 + (swz(ch, row) << 4));
#pragma unroll
                    for (int mt = 0; mt < 2; mt++) {
                        mma16h(o[mt][2 * np],     pf[ktl][mt], b[0], b[1]);
                        mma16h(o[mt][2 * np + 1], pf[ktl][mt], b[2], b[3]);
                    }
                }
            }
        }
        __syncthreads();

        if (j < 30 && tid == 0) {
            uint32_t mb = sb + MB_ + ((j & 1) << 3);
            MBARRIER_EXPECT_TX(mb, 32768u);
            bulk_g2s(sb + KB_ + ((j & 1) << 14),
                     Kg + (size_t)(j + 2) * 64 * 128, 16384u, mb);
            bulk_g2s(sb + VB_ + ((j & 1) << 14),
                     Vg + (size_t)(j + 2) * 64 * 128, 16384u, mb);
        }
    }

    // ================= fused out-projection epilogue =================
    MBARRIER_WAIT_PARITY(sb + MB_ + 16, 0);   // Wout arrived long ago

    const uint32_t wb4 = sb + WB_
        + (((lane >> 4) << 3) + (lane & 7)) * 272 + (((lane >> 3) & 1) << 4);

#pragma unroll
    for (int mt = 0; mt < 2; mt++) {
        const float inv0 = 1.f / lacc[mt][0];   // row g
        const float inv1 = 1.f / lacc[mt][2];   // row g+8

        // O C-frags -> fp16 A-frags (normalized). C layout == A layout.
        uint32_t af[8][4];
#pragma unroll
        for (int kt = 0; kt < 8; kt++) {
            af[kt][0] = f2h2(o[mt][2 * kt][1] * inv0,     o[mt][2 * kt][0] * inv0);
            af[kt][1] = f2h2(o[mt][2 * kt][3] * inv1,     o[mt][2 * kt][2] * inv1);
            af[kt][2] = f2h2(o[mt][2 * kt + 1][1] * inv0, o[mt][2 * kt + 1][0] * inv0);
            af[kt][3] = f2h2(o[mt][2 * kt + 1][3] * inv1, o[mt][2 * kt + 1][2] * inv1);
        }

        float oo[16][4];
#pragma unroll
        for (int nt = 0; nt < 16; nt++)
#pragma unroll
            for (int c = 0; c < 4; c++) oo[nt][c] = 0.f;

#pragma unroll
        for (int kt = 0; kt < 8; kt++)
#pragma unroll
            for (int ntp = 0; ntp < 8; ntp++) {
                uint32_t b[4];
                ldmx4(b, wb4 + ntp * 4352 + (kt << 5));
                mma16h(oo[2 * ntp],     af[kt], b[0], b[1]);
                mma16h(oo[2 * ntp + 1], af[kt], b[2], b[3]);
            }

        const size_t r0 = (size_t)bh * 2048 + i0 + (w << 5) + (mt << 4) + g;
        float* O0 = outp + r0 * 128;
        float* O1 = O0 + 8 * 128;
#pragma unroll
        for (int nt = 0; nt < 16; nt++) {
            const int col = (nt << 3) + (tg << 1);
            float b0 = __ldg(&bias[col]);
            float b1 = __ldg(&bias[col + 1]);
            *(float2*)&O0[col] = make_float2(oo[nt][0] + b0, oo[nt][1] + b1);
            *(float2*)&O1[col] = make_float2(oo[nt][2] + b0, oo[nt][3] + b1);
        }
    }
}

// ===========================================================================

extern "C" void kernel_launch(void* const* d_in, const int* in_sizes, int n_in,
                              void* d_out, int out_size)
{
    const float* q    = (const float*)d_in[0];
    const float* kv   = (const float*)d_in[1];
    const float* Wq   = (const float*)d_in[2];
    const float* Wkv  = (const float*)d_in[3];
    const float* Wout = (const float*)d_in[4];
    const float* bout = (const float*)d_in[5];
    float* out = (float*)d_out;

    __half *qhp, *khp, *vhp, *whp;
    cudaGetSymbolAddress((void**)&qhp, g_qh);
    cudaGetSymbolAddress((void**)&khp, g_kh);
    cudaGetSymbolAddress((void**)&vhp, g_vh);
    cudaGetSymbolAddress((void**)&whp, g_wh);

    cudaFuncSetAttribute((const void*)proj_q_kernel,
                         cudaFuncAttributeMaxDynamicSharedMemorySize, 2 * PL);
    cudaFuncSetAttribute((const void*)proj_kv_kernel,
                         cudaFuncAttributeMaxDynamicSharedMemorySize, 3 * PL);
    cudaFuncSetAttribute((const void*)attn_mma_kernel,
                         cudaFuncAttributeMaxDynamicSharedMemorySize, ATT_BYTES);

    // q' = (q @ Wq^T) * QSCALE -> fp16; CTA 0 also converts Wout -> g_wh
    proj_q_kernel<<<dim3(1, 1024), 256, 2 * PL>>>(q, Wq, Wout, qhp, whp);
    // k' + v' in one kernel (kv staged once)
    proj_kv_kernel<<<dim3(1, 1024), 256, 3 * PL>>>(kv, Wkv, khp, vhp);
    // flash attention + fused out-projection (Wout prefetched via bulk copy)
    attn_mma_kernel<<<dim3(16, 64), 128, ATT_BYTES>>>(
        qhp, khp, vhp, whp, bout, out);
}